// round 7
// baseline (speedup 1.0000x reference)
#include <cuda_runtime.h>
#include <cuda_bf16.h>
#include <cstdint>
#include <math.h>

#define Bsz  4
#define CIN  256
#define COUT 128
#define HW   4096   // 64*64

// ---------------- device scratch ----------------
__device__ float g_xt[Bsz * HW * CIN];        // NHWC x (16 MB)
__device__ float g_off[Bsz][27][HW];          // dy(0-8), dx(9-17), m(18-26)
__device__ float g_out1[Bsz][COUT][HW];       // deform conv output (pre-BN1)
__device__ float g_wT[2304 * COUT];           // dcn_w reordered: [cb16][k][c][o]
__device__ float g_wT2[16 * COUT * COUT];     // [ky*4+kx][c][o]
__device__ float g_bn1s[COUT], g_bn1b[COUT];
__device__ float g_bn2s[COUT], g_bn2b[COUT];
__device__ float g_psum[2][512][2];

// ---------------- weight prep ----------------
__global__ void prep_kernel(const float* __restrict__ dcn_w,
                            const float* __restrict__ up_w) {
    int i = blockIdx.x * blockDim.x + threadIdx.x;
    if (i < 2304 * COUT) {
        int ck = i >> 7, o = i & 127;
        int cb = ck / 144;            // 16-channel chunk
        int r  = ck - cb * 144;
        int k  = r >> 4;              // tap
        int c  = r & 15;
        int cg = cb * 16 + c;
        g_wT[i] = dcn_w[o * 2304 + cg * 9 + k];
    }
    if (i < 16 * COUT * COUT) {
        int o  = i & 127;
        int c  = (i >> 7) & 127;
        int kk = i >> 14;
        int ky = kk >> 2, kx = kk & 3;
        g_wT2[i] = up_w[((c * COUT + o) * 4 + (3 - ky)) * 4 + (3 - kx)];
    }
}

// ---------------- NCHW -> NHWC transpose of x ----------------
__global__ void nhwc_kernel(const float* __restrict__ x) {
    __shared__ float t[32][33];
    int b  = blockIdx.z;
    int p0 = blockIdx.x * 32;
    int c0 = blockIdx.y * 32;
    int tx = threadIdx.x, ty = threadIdx.y;
#pragma unroll
    for (int i = 0; i < 4; i++)
        t[ty + i * 8][tx] = x[((size_t)(b * CIN + c0 + ty + i * 8)) * HW + p0 + tx];
    __syncthreads();
#pragma unroll
    for (int i = 0; i < 4; i++)
        g_xt[((size_t)(b * HW + p0 + ty + i * 8)) * CIN + c0 + tx] = t[tx][ty + i * 8];
}

// ---------------- offset conv: 3x3, 256 -> 27, pad 1 ----------------
#define OG 8
__global__ void offset_conv_kernel(const float* __restrict__ x,
                                   const float* __restrict__ off_w,
                                   const float* __restrict__ off_b) {
    int bh = blockIdx.x;
    int b = bh >> 6, h = bh & 63;
    int g = threadIdx.x >> 6;
    int w = threadIdx.x & 63;
    __shared__ float srow[OG][3][64];
    __shared__ float sws[OG][324];
    __shared__ float red[OG][64];

    float acc[27];
#pragma unroll
    for (int i = 0; i < 27; i++) acc[i] = 0.f;

    const float* xb = x + (size_t)b * CIN * HW;
    for (int cc = 0; cc < CIN / OG; cc++) {
        int c = g * (CIN / OG) + cc;
#pragma unroll
        for (int r = 0; r < 3; r++) {
            int hh = h + r - 1;
            srow[g][r][w] = (hh >= 0 && hh < 64) ? xb[(size_t)c * HW + hh * 64 + w] : 0.f;
        }
        const float* wc = off_w + c * 9;
        for (int j = w; j < 243; j += 64) {
            int oc = j / 9, tap = j - oc * 9;
            sws[g][oc * 12 + tap] = wc[(size_t)oc * (CIN * 9) + tap];
        }
        __syncthreads();
        float xv[9];
#pragma unroll
        for (int tap = 0; tap < 9; tap++) {
            int col = w + (tap % 3) - 1;
            xv[tap] = (col >= 0 && col < 64) ? srow[g][tap / 3][col] : 0.f;
        }
#pragma unroll
        for (int oc = 0; oc < 27; oc++) {
            const float4* wv = (const float4*)&sws[g][oc * 12];
            float4 w0 = wv[0], w1 = wv[1], w2 = wv[2];
            float a = acc[oc];
            a = fmaf(w0.x, xv[0], a); a = fmaf(w0.y, xv[1], a);
            a = fmaf(w0.z, xv[2], a); a = fmaf(w0.w, xv[3], a);
            a = fmaf(w1.x, xv[4], a); a = fmaf(w1.y, xv[5], a);
            a = fmaf(w1.z, xv[6], a); a = fmaf(w1.w, xv[7], a);
            a = fmaf(w2.x, xv[8], a);
            acc[oc] = a;
        }
        __syncthreads();
    }
    for (int oc = 0; oc < 27; oc++) {
        red[g][w] = acc[oc];
        __syncthreads();
        if (g == 0) {
            float v = red[0][w] + red[1][w] + red[2][w] + red[3][w]
                    + red[4][w] + red[5][w] + red[6][w] + red[7][w] + off_b[oc];
            if (oc >= 18) v = 1.f / (1.f + __expf(-v));
            g_off[b][oc][h * 64 + w] = v;
        }
        __syncthreads();
    }
}

// ---------------- deformable conv implicit GEMM (v6) ----------------
// grid = B*64 (block = one 64-px row), block = 256: thread = 4 oc x 8 px.
// dynamic smem: ssam[2][144*SSPD] | sidx[576] int4 | swt[576] float4
#define SSPD 68
#define SSAM_BYTES (2 * 144 * SSPD * 4)
#define SIDX_BYTES (576 * 16)
#define DEF_SMEM (SSAM_BYTES + 2 * SIDX_BYTES)

__device__ __forceinline__ void dgather(int tid, int cb, float* sbuf,
                                        const float* __restrict__ xtb,
                                        const int4* sidx, const float4* swt) {
    for (int it = tid; it < 2304; it += 256) {
        int c  = it & 15;
        int kp = it >> 4;          // 0..143
        int k  = kp >> 4;          // 0..8
        int p4 = kp & 15;          // 0..15
        const float* xc = xtb + cb * 16 + c;
        float4 v;
        float* vp = &v.x;
#pragma unroll
        for (int j = 0; j < 4; j++) {
            int e = k * 64 + p4 * 4 + j;
            int4 id = sidx[e];
            float4 wt = swt[e];
            float r =      wt.x * __ldg(xc + id.x * CIN);
            r = fmaf(wt.y, __ldg(xc + id.y * CIN), r);
            r = fmaf(wt.z, __ldg(xc + id.z * CIN), r);
            r = fmaf(wt.w, __ldg(xc + id.w * CIN), r);
            vp[j] = r;
        }
        *(float4*)&sbuf[(k * 16 + c) * SSPD + p4 * 4] = v;
    }
}

__global__ void __launch_bounds__(256) deform_kernel(const float* __restrict__ dcn_b) {
    extern __shared__ __align__(16) char dyn[];
    float* ssam = (float*)dyn;
    int4*  sidx = (int4*)(dyn + SSAM_BYTES);
    float4* swt = (float4*)(dyn + SSAM_BYTES + SIDX_BYTES);

    int blk = blockIdx.x;
    int b = blk >> 6;
    int h = blk & 63;
    int p0 = h << 6;               // full row of 64 px
    int tid = threadIdx.x;

    for (int e = tid; e < 576; e += 256) {
        int k = e >> 6, p = e & 63;
        float dy = g_off[b][k][p0 + p];
        float dx = g_off[b][9 + k][p0 + p];
        float m  = g_off[b][18 + k][p0 + p];
        float py = dy + (float)(k / 3 - 1 + h);
        float px = dx + (float)(k % 3 - 1 + p);
        float y0f = floorf(py), x0f = floorf(px);
        int y0 = (int)y0f, x0i = (int)x0f;
        float wy = py - y0f, wx = px - x0f;
        float w00 = (1.f - wy) * (1.f - wx) * m;
        float w01 = (1.f - wy) * wx * m;
        float w10 = wy * (1.f - wx) * m;
        float w11 = wy * wx * m;
        int y1 = y0 + 1, x1i = x0i + 1;
        bool y0v = (unsigned)y0  < 64u, y1v = (unsigned)y1  < 64u;
        bool x0v = (unsigned)x0i < 64u, x1v = (unsigned)x1i < 64u;
        int y0c = min(max(y0, 0), 63),  y1c = min(max(y1, 0), 63);
        int x0c = min(max(x0i, 0), 63), x1c = min(max(x1i, 0), 63);
        sidx[e] = make_int4(y0c * 64 + x0c, y0c * 64 + x1c,
                            y1c * 64 + x0c, y1c * 64 + x1c);
        swt[e] = make_float4(y0v && x0v ? w00 : 0.f,
                             y0v && x1v ? w01 : 0.f,
                             y1v && x0v ? w10 : 0.f,
                             y1v && x1v ? w11 : 0.f);
    }
    __syncthreads();

    int oc0 = tid & 31;              // covers oc0, +32, +64, +96
    int pbase = (tid >> 5) << 3;     // 0..56 step 8

    unsigned long long acc[16];      // [oci*4 + pair]
#pragma unroll
    for (int i = 0; i < 16; i++) acc[i] = 0ull;

    unsigned sbase = (unsigned)__cvta_generic_to_shared(ssam) + pbase * 4;
    const float* xtb = g_xt + (size_t)b * HW * CIN;

    dgather(tid, 0, ssam, xtb, sidx, swt);
    __syncthreads();

#pragma unroll 1
    for (int cb = 0; cb < 16; cb++) {
        if (cb < 15) dgather(tid, cb + 1, ssam + ((cb + 1) & 1) * (144 * SSPD), xtb, sidx, swt);
        const float* wp = g_wT + (size_t)cb * 144 * 128 + oc0;
        unsigned a0 = sbase + (cb & 1) * (144 * SSPD * 4);
#pragma unroll 2
        for (int ckl = 0; ckl < 144; ckl++) {
            float wv0 = __ldg(wp + ckl * 128);
            float wv1 = __ldg(wp + ckl * 128 + 32);
            float wv2 = __ldg(wp + ckl * 128 + 64);
            float wv3 = __ldg(wp + ckl * 128 + 96);
            unsigned long long w0, w1, w2, w3;
            asm("mov.b64 %0, {%1, %1};" : "=l"(w0) : "f"(wv0));
            asm("mov.b64 %0, {%1, %1};" : "=l"(w1) : "f"(wv1));
            asm("mov.b64 %0, {%1, %1};" : "=l"(w2) : "f"(wv2));
            asm("mov.b64 %0, {%1, %1};" : "=l"(w3) : "f"(wv3));
            unsigned a = a0 + ckl * (SSPD * 4);
            unsigned long long s0, s1, s2, s3;
            asm volatile("ld.shared.v2.b64 {%0, %1}, [%2];" : "=l"(s0), "=l"(s1) : "r"(a));
            asm volatile("ld.shared.v2.b64 {%0, %1}, [%2];" : "=l"(s2), "=l"(s3) : "r"(a + 16));
            asm("fma.rn.f32x2 %0, %1, %2, %0;" : "+l"(acc[0])  : "l"(w0), "l"(s0));
            asm("fma.rn.f32x2 %0, %1, %2, %0;" : "+l"(acc[1])  : "l"(w0), "l"(s1));
            asm("fma.rn.f32x2 %0, %1, %2, %0;" : "+l"(acc[2])  : "l"(w0), "l"(s2));
            asm("fma.rn.f32x2 %0, %1, %2, %0;" : "+l"(acc[3])  : "l"(w0), "l"(s3));
            asm("fma.rn.f32x2 %0, %1, %2, %0;" : "+l"(acc[4])  : "l"(w1), "l"(s0));
            asm("fma.rn.f32x2 %0, %1, %2, %0;" : "+l"(acc[5])  : "l"(w1), "l"(s1));
            asm("fma.rn.f32x2 %0, %1, %2, %0;" : "+l"(acc[6])  : "l"(w1), "l"(s2));
            asm("fma.rn.f32x2 %0, %1, %2, %0;" : "+l"(acc[7])  : "l"(w1), "l"(s3));
            asm("fma.rn.f32x2 %0, %1, %2, %0;" : "+l"(acc[8])  : "l"(w2), "l"(s0));
            asm("fma.rn.f32x2 %0, %1, %2, %0;" : "+l"(acc[9])  : "l"(w2), "l"(s1));
            asm("fma.rn.f32x2 %0, %1, %2, %0;" : "+l"(acc[10]) : "l"(w2), "l"(s2));
            asm("fma.rn.f32x2 %0, %1, %2, %0;" : "+l"(acc[11]) : "l"(w2), "l"(s3));
            asm("fma.rn.f32x2 %0, %1, %2, %0;" : "+l"(acc[12]) : "l"(w3), "l"(s0));
            asm("fma.rn.f32x2 %0, %1, %2, %0;" : "+l"(acc[13]) : "l"(w3), "l"(s1));
            asm("fma.rn.f32x2 %0, %1, %2, %0;" : "+l"(acc[14]) : "l"(w3), "l"(s2));
            asm("fma.rn.f32x2 %0, %1, %2, %0;" : "+l"(acc[15]) : "l"(w3), "l"(s3));
        }
        __syncthreads();
    }

#pragma unroll
    for (int oci = 0; oci < 4; oci++) {
        int oc = oc0 + oci * 32;
        float bias = dcn_b[oc];
        float* o = &g_out1[b][oc][p0 + pbase];
#pragma unroll
        for (int q = 0; q < 2; q++) {
            float e0, e1, e2, e3;
            asm("mov.b64 {%0, %1}, %2;" : "=f"(e0), "=f"(e1) : "l"(acc[oci*4 + 2*q]));
            asm("mov.b64 {%0, %1}, %2;" : "=f"(e2), "=f"(e3) : "l"(acc[oci*4 + 2*q + 1]));
            ((float4*)o)[q] = make_float4(e0 + bias, e1 + bias, e2 + bias, e3 + bias);
        }
    }
}

// ---------------- BN stats: 2-stage deterministic reduction ----------------
__global__ void bn_partial_kernel(const float* __restrict__ ext, int which) {
    int bx = blockIdx.x;
    int c = bx >> 2, b = bx & 3;
    const float* plane = which ? ext + (size_t)(b * 128 + c) * 16384
                               : &g_out1[b][c][0];
    int n4 = which ? 4096 : 1024;
    float s = 0.f, s2 = 0.f;
    const float4* p4 = (const float4*)plane;
    for (int i = threadIdx.x; i < n4; i += 128) {
        float4 v = p4[i];
        s  += v.x + v.y + v.z + v.w;
        s2 += v.x*v.x + v.y*v.y + v.z*v.z + v.w*v.w;
    }
    __shared__ float rs[128], rq[128];
    rs[threadIdx.x] = s; rq[threadIdx.x] = s2;
    __syncthreads();
    for (int st = 64; st > 0; st >>= 1) {
        if (threadIdx.x < st) {
            rs[threadIdx.x] += rs[threadIdx.x + st];
            rq[threadIdx.x] += rq[threadIdx.x + st];
        }
        __syncthreads();
    }
    if (threadIdx.x == 0) {
        g_psum[which][bx][0] = rs[0];
        g_psum[which][bx][1] = rq[0];
    }
}

__global__ void bn_final_kernel(const float* __restrict__ gamma,
                                const float* __restrict__ beta, int which) {
    int c = threadIdx.x;
    float s = 0.f, s2 = 0.f;
#pragma unroll
    for (int b = 0; b < 4; b++) {
        s  += g_psum[which][c * 4 + b][0];
        s2 += g_psum[which][c * 4 + b][1];
    }
    float n  = which ? 65536.f : 16384.f;
    float mu = s / n;
    float var = s2 / n - mu * mu;
    float sc = gamma[c] * rsqrtf(var + 1e-5f);
    float sh = beta[c] - mu * sc;
    if (which == 0) { g_bn1s[c] = sc; g_bn1b[c] = sh; }
    else            { g_bn2s[c] = sc; g_bn2b[c] = sh; }
}

// ---------------- transposed conv as parity GEMMs (R3-v2) ----------
#define SSP 68
__global__ void __launch_bounds__(128) transp_kernel(float* __restrict__ out) {
    int blk = blockIdx.x;
    int u   = blk & 63;
    int par = (blk >> 6) & 3;
    int b   = blk >> 8;
    int py = par >> 1, px = par & 1;
    int tid = threadIdx.x;

    __shared__ float srow[16 * 2 * 64];              // [ci][t][col], BN1+ReLU applied
    __shared__ __align__(16) float ssam[64 * SSP];   // [ck=ci*4+t*2+s][p]

    int oc0 = tid & 63;
    int pbase = (tid >> 6) << 5;      // 0 or 32

    unsigned long long acc[32];       // [0..15]=oc0, [16..31]=oc0+64
#pragma unroll
    for (int i = 0; i < 32; i++) acc[i] = 0ull;

    unsigned sbase = (unsigned)__cvta_generic_to_shared(ssam);

#pragma unroll 1
    for (int cb = 0; cb < 8; cb++) {                 // 16 channels per chunk
        for (int e = tid; e < 16 * 2 * 16; e += 128) {
            int ci = e >> 5;
            int tt = (e >> 4) & 1;
            int f4 = e & 15;
            int c  = cb * 16 + ci;
            int row = u + py - 1 + tt;
            float4 v = make_float4(0.f, 0.f, 0.f, 0.f);
            if ((unsigned)row < 64u) {
                float4 r = *(const float4*)&g_out1[b][c][row * 64 + f4 * 4];
                float sc = g_bn1s[c], sh = g_bn1b[c];
                v.x = fmaxf(fmaf(r.x, sc, sh), 0.f);
                v.y = fmaxf(fmaf(r.y, sc, sh), 0.f);
                v.z = fmaxf(fmaf(r.z, sc, sh), 0.f);
                v.w = fmaxf(fmaf(r.w, sc, sh), 0.f);
            }
            *(float4*)&srow[(ci * 2 + tt) * 64 + f4 * 4] = v;
        }
        __syncthreads();
        for (int e = tid; e < 64 * 64; e += 128) {
            int ck = e >> 6;
            int p  = e & 63;
            int ci = ck >> 2;
            int tt = (ck >> 1) & 1;
            int s  = ck & 1;
            int col = p + px - 1 + s;
            float v = (col >= 0 && col < 64) ? srow[(ci * 2 + tt) * 64 + col] : 0.f;
            ssam[ck * SSP + p] = v;
        }
        __syncthreads();
#pragma unroll 1
        for (int ts = 0; ts < 4; ts++) {
            int tt = ts >> 1, s = ts & 1;
            int kk = (py + 2 * tt) * 4 + (px + 2 * s);
            const float* wp = g_wT2 + (size_t)kk * 16384 + cb * 16 * 128 + oc0;
            for (int ci = 0; ci < 16; ci++) {
                float wv0 = __ldg(wp + ci * 128);
                float wv1 = __ldg(wp + ci * 128 + 64);
                unsigned long long w0pk, w1pk;
                asm("mov.b64 %0, {%1, %1};" : "=l"(w0pk) : "f"(wv0));
                asm("mov.b64 %0, {%1, %1};" : "=l"(w1pk) : "f"(wv1));
                int ck = ci * 4 + ts;
                unsigned a = sbase + (ck * SSP + pbase) * 4;
#pragma unroll
                for (int q = 0; q < 8; q++) {
                    unsigned long long sa, sb;
                    asm volatile("ld.shared.v2.b64 {%0, %1}, [%2];"
                                 : "=l"(sa), "=l"(sb) : "r"(a + q * 16));
                    asm("fma.rn.f32x2 %0, %1, %2, %0;" : "+l"(acc[2*q])      : "l"(w0pk), "l"(sa));
                    asm("fma.rn.f32x2 %0, %1, %2, %0;" : "+l"(acc[2*q+1])    : "l"(w0pk), "l"(sb));
                    asm("fma.rn.f32x2 %0, %1, %2, %0;" : "+l"(acc[16+2*q])   : "l"(w1pk), "l"(sa));
                    asm("fma.rn.f32x2 %0, %1, %2, %0;" : "+l"(acc[16+2*q+1]) : "l"(w1pk), "l"(sb));
                }
            }
        }
        __syncthreads();
    }

    int y = 2 * u + py;
    float* o0 = out + (((size_t)(b * 128 + oc0)      * 128 + y) * 128) + px + 2 * pbase;
    float* o1 = out + (((size_t)(b * 128 + oc0 + 64) * 128 + y) * 128) + px + 2 * pbase;
#pragma unroll
    for (int q = 0; q < 8; q++) {
        float e0, e1, e2, e3;
        asm("mov.b64 {%0, %1}, %2;" : "=f"(e0), "=f"(e1) : "l"(acc[2*q]));
        asm("mov.b64 {%0, %1}, %2;" : "=f"(e2), "=f"(e3) : "l"(acc[2*q+1]));
        o0[(4*q + 0) * 2] = e0; o0[(4*q + 1) * 2] = e1;
        o0[(4*q + 2) * 2] = e2; o0[(4*q + 3) * 2] = e3;
        asm("mov.b64 {%0, %1}, %2;" : "=f"(e0), "=f"(e1) : "l"(acc[16+2*q]));
        asm("mov.b64 {%0, %1}, %2;" : "=f"(e2), "=f"(e3) : "l"(acc[16+2*q+1]));
        o1[(4*q + 0) * 2] = e0; o1[(4*q + 1) * 2] = e1;
        o1[(4*q + 2) * 2] = e2; o1[(4*q + 3) * 2] = e3;
    }
}

// ---------------- BN2 apply + ReLU, in place on d_out ----------------
__global__ void bn_apply_kernel(float* __restrict__ out) {
    int i = blockIdx.x * 256 + threadIdx.x;
    int c = (i >> 12) & 127;
    float sc = g_bn2s[c], sh = g_bn2b[c];
    float4 v = ((float4*)out)[i];
    v.x = fmaxf(v.x * sc + sh, 0.f);
    v.y = fmaxf(v.y * sc + sh, 0.f);
    v.z = fmaxf(v.z * sc + sh, 0.f);
    v.w = fmaxf(v.w * sc + sh, 0.f);
    ((float4*)out)[i] = v;
}

// ---------------- launch ----------------
extern "C" void kernel_launch(void* const* d_in, const int* in_sizes, int n_in,
                              void* d_out, int out_size) {
    const float* x     = (const float*)d_in[0];
    const float* off_w = (const float*)d_in[1];
    const float* off_b = (const float*)d_in[2];
    const float* dcn_w = (const float*)d_in[3];
    const float* dcn_b = (const float*)d_in[4];
    const float* bn1_g = (const float*)d_in[5];
    const float* bn1_b = (const float*)d_in[6];
    const float* up_w  = (const float*)d_in[7];
    const float* bn2_g = (const float*)d_in[8];
    const float* bn2_b = (const float*)d_in[9];
    float* out = (float*)d_out;

    cudaFuncSetAttribute(deform_kernel,
                         cudaFuncAttributeMaxDynamicSharedMemorySize, DEF_SMEM);

    prep_kernel<<<1152, 256>>>(dcn_w, up_w);
    nhwc_kernel<<<dim3(128, 8, 4), dim3(32, 8)>>>(x);
    offset_conv_kernel<<<256, 512>>>(x, off_w, off_b);
    deform_kernel<<<256, 256, DEF_SMEM>>>(dcn_b);
    bn_partial_kernel<<<512, 128>>>(nullptr, 0);
    bn_final_kernel<<<1, 128>>>(bn1_g, bn1_b, 0);
    transp_kernel<<<1024, 128>>>(out);
    bn_partial_kernel<<<512, 128>>>(out, 1);
    bn_final_kernel<<<1, 128>>>(bn2_g, bn2_b, 1);
    bn_apply_kernel<<<8192, 256>>>(out);
}

// round 8
// speedup vs baseline: 1.0978x; 1.0978x over previous
#include <cuda_runtime.h>
#include <cuda_bf16.h>
#include <cstdint>
#include <math.h>

#define Bsz  4
#define CIN  256
#define COUT 128
#define HW   4096   // 64*64

// ---------------- device scratch ----------------
__device__ float g_xt[Bsz * HW * CIN];        // NHWC x (16 MB)
__device__ float g_off[Bsz][27][HW];          // dy(0-8), dx(9-17), m(18-26)
__device__ float g_out1[Bsz][COUT][HW];       // deform conv output (pre-BN1)
__device__ float g_wT[2304 * COUT];           // dcn_w reordered: [cb16][k][c][o]
__device__ float g_wT2[16 * COUT * COUT];     // [ky*4+kx][c][o]
__device__ float g_bn1s[COUT], g_bn1b[COUT];
__device__ float g_bn2s[COUT], g_bn2b[COUT];
__device__ float g_psum[2][512][2];

// ---------------- weight prep ----------------
__global__ void prep_kernel(const float* __restrict__ dcn_w,
                            const float* __restrict__ up_w) {
    int i = blockIdx.x * blockDim.x + threadIdx.x;
    if (i < 2304 * COUT) {
        int ck = i >> 7, o = i & 127;
        int cb = ck / 144;            // 16-channel chunk
        int r  = ck - cb * 144;
        int k  = r >> 4;              // tap
        int c  = r & 15;
        int cg = cb * 16 + c;
        g_wT[i] = dcn_w[o * 2304 + cg * 9 + k];
    }
    if (i < 16 * COUT * COUT) {
        int o  = i & 127;
        int c  = (i >> 7) & 127;
        int kk = i >> 14;
        int ky = kk >> 2, kx = kk & 3;
        g_wT2[i] = up_w[((c * COUT + o) * 4 + (3 - ky)) * 4 + (3 - kx)];
    }
}

// ---------------- NCHW -> NHWC transpose of x ----------------
__global__ void nhwc_kernel(const float* __restrict__ x) {
    __shared__ float t[32][33];
    int b  = blockIdx.z;
    int p0 = blockIdx.x * 32;
    int c0 = blockIdx.y * 32;
    int tx = threadIdx.x, ty = threadIdx.y;
#pragma unroll
    for (int i = 0; i < 4; i++)
        t[ty + i * 8][tx] = x[((size_t)(b * CIN + c0 + ty + i * 8)) * HW + p0 + tx];
    __syncthreads();
#pragma unroll
    for (int i = 0; i < 4; i++)
        g_xt[((size_t)(b * HW + p0 + ty + i * 8)) * CIN + c0 + tx] = t[tx][ty + i * 8];
}

// ---------------- offset conv: 3x3, 256 -> 27, pad 1 ----------------
#define OG 8
__global__ void offset_conv_kernel(const float* __restrict__ x,
                                   const float* __restrict__ off_w,
                                   const float* __restrict__ off_b) {
    int bh = blockIdx.x;
    int b = bh >> 6, h = bh & 63;
    int g = threadIdx.x >> 6;
    int w = threadIdx.x & 63;
    __shared__ float srow[OG][3][64];
    __shared__ float sws[OG][324];
    __shared__ float red[OG][64];

    float acc[27];
#pragma unroll
    for (int i = 0; i < 27; i++) acc[i] = 0.f;

    const float* xb = x + (size_t)b * CIN * HW;
    for (int cc = 0; cc < CIN / OG; cc++) {
        int c = g * (CIN / OG) + cc;
#pragma unroll
        for (int r = 0; r < 3; r++) {
            int hh = h + r - 1;
            srow[g][r][w] = (hh >= 0 && hh < 64) ? xb[(size_t)c * HW + hh * 64 + w] : 0.f;
        }
        const float* wc = off_w + c * 9;
        for (int j = w; j < 243; j += 64) {
            int oc = j / 9, tap = j - oc * 9;
            sws[g][oc * 12 + tap] = wc[(size_t)oc * (CIN * 9) + tap];
        }
        __syncthreads();
        float xv[9];
#pragma unroll
        for (int tap = 0; tap < 9; tap++) {
            int col = w + (tap % 3) - 1;
            xv[tap] = (col >= 0 && col < 64) ? srow[g][tap / 3][col] : 0.f;
        }
#pragma unroll
        for (int oc = 0; oc < 27; oc++) {
            const float4* wv = (const float4*)&sws[g][oc * 12];
            float4 w0 = wv[0], w1 = wv[1], w2 = wv[2];
            float a = acc[oc];
            a = fmaf(w0.x, xv[0], a); a = fmaf(w0.y, xv[1], a);
            a = fmaf(w0.z, xv[2], a); a = fmaf(w0.w, xv[3], a);
            a = fmaf(w1.x, xv[4], a); a = fmaf(w1.y, xv[5], a);
            a = fmaf(w1.z, xv[6], a); a = fmaf(w1.w, xv[7], a);
            a = fmaf(w2.x, xv[8], a);
            acc[oc] = a;
        }
        __syncthreads();
    }
    for (int oc = 0; oc < 27; oc++) {
        red[g][w] = acc[oc];
        __syncthreads();
        if (g == 0) {
            float v = red[0][w] + red[1][w] + red[2][w] + red[3][w]
                    + red[4][w] + red[5][w] + red[6][w] + red[7][w] + off_b[oc];
            if (oc >= 18) v = 1.f / (1.f + __expf(-v));
            g_off[b][oc][h * 64 + w] = v;
        }
        __syncthreads();
    }
}

// ---------------- deformable conv implicit GEMM (R4-v3, best measured) -----
// grid = B*128 (block = 32 px), block = 256: thread = (oc0, oc0+64) x 8 px.
#define SSP2 36
__device__ __forceinline__ void dgather(int tid, int cb, float* sbuf,
                                        const float* __restrict__ xtb,
                                        const int4* sidx, const float4* swt) {
    for (int it = tid; it < 1152; it += 256) {
        int c = it & 15;
        int kp = it >> 4;          // 0..71
        int k = kp >> 3;
        int p4 = kp & 7;
        const float* xc = xtb + cb * 16 + c;
        float4 v;
        float* vp = &v.x;
#pragma unroll
        for (int j = 0; j < 4; j++) {
            int e = k * 32 + p4 * 4 + j;
            int4 id = sidx[e];
            float4 wt = swt[e];
            float r =      wt.x * __ldg(xc + id.x * CIN);
            r = fmaf(wt.y, __ldg(xc + id.y * CIN), r);
            r = fmaf(wt.z, __ldg(xc + id.z * CIN), r);
            r = fmaf(wt.w, __ldg(xc + id.w * CIN), r);
            vp[j] = r;
        }
        *(float4*)&sbuf[(k * 16 + c) * SSP2 + p4 * 4] = v;
    }
}

__global__ void __launch_bounds__(256) deform_kernel(const float* __restrict__ dcn_b) {
    int blk = blockIdx.x;
    int b = blk >> 7;
    int t = blk & 127;
    int h = t >> 1;
    int w0 = (t & 1) << 5;
    int p0 = h * 64 + w0;
    int tid = threadIdx.x;

    __shared__ int4  sidx[288];
    __shared__ float4 swt[288];
    __shared__ __align__(16) float ssam[2][144 * SSP2];

    for (int e = tid; e < 288; e += 256) {
        int k = e >> 5, p = e & 31;
        float dy = g_off[b][k][p0 + p];
        float dx = g_off[b][9 + k][p0 + p];
        float m  = g_off[b][18 + k][p0 + p];
        float py = dy + (float)(k / 3 - 1 + h);
        float px = dx + (float)(k % 3 - 1 + w0 + p);
        float y0f = floorf(py), x0f = floorf(px);
        int y0 = (int)y0f, x0i = (int)x0f;
        float wy = py - y0f, wx = px - x0f;
        float w00 = (1.f - wy) * (1.f - wx) * m;
        float w01 = (1.f - wy) * wx * m;
        float w10 = wy * (1.f - wx) * m;
        float w11 = wy * wx * m;
        int y1 = y0 + 1, x1i = x0i + 1;
        bool y0v = (unsigned)y0  < 64u, y1v = (unsigned)y1  < 64u;
        bool x0v = (unsigned)x0i < 64u, x1v = (unsigned)x1i < 64u;
        int y0c = min(max(y0, 0), 63),  y1c = min(max(y1, 0), 63);
        int x0c = min(max(x0i, 0), 63), x1c = min(max(x1i, 0), 63);
        sidx[e] = make_int4(y0c * 64 + x0c, y0c * 64 + x1c,
                            y1c * 64 + x0c, y1c * 64 + x1c);
        swt[e] = make_float4(y0v && x0v ? w00 : 0.f,
                             y0v && x1v ? w01 : 0.f,
                             y1v && x0v ? w10 : 0.f,
                             y1v && x1v ? w11 : 0.f);
    }
    __syncthreads();

    int oc0 = tid & 63;
    int pbase = (tid >> 6) << 3;     // 0,8,16,24

    unsigned long long acc[8];       // [0..3]=oc0, [4..7]=oc0+64 (4 px-pairs)
#pragma unroll
    for (int i = 0; i < 8; i++) acc[i] = 0ull;

    unsigned sbase = (unsigned)__cvta_generic_to_shared(&ssam[0][0]);
    const float* xtb = g_xt + (size_t)b * HW * CIN;

    dgather(tid, 0, &ssam[0][0], xtb, sidx, swt);
    __syncthreads();

#pragma unroll 1
    for (int cb = 0; cb < 16; cb++) {
        if (cb < 15) dgather(tid, cb + 1, &ssam[(cb + 1) & 1][0], xtb, sidx, swt);
        const float* wp = g_wT + (size_t)cb * 144 * 128 + oc0;
        unsigned a0 = sbase + (cb & 1) * (144 * SSP2 * 4) + pbase * 4;
#pragma unroll 4
        for (int ckl = 0; ckl < 144; ckl++) {
            float wv0 = __ldg(wp + ckl * 128);
            float wv1 = __ldg(wp + ckl * 128 + 64);
            unsigned long long w0pk, w1pk;
            asm("mov.b64 %0, {%1, %1};" : "=l"(w0pk) : "f"(wv0));
            asm("mov.b64 %0, {%1, %1};" : "=l"(w1pk) : "f"(wv1));
            unsigned a = a0 + ckl * (SSP2 * 4);
            unsigned long long sa, sb, sc, sd;
            asm volatile("ld.shared.v2.b64 {%0, %1}, [%2];" : "=l"(sa), "=l"(sb) : "r"(a));
            asm volatile("ld.shared.v2.b64 {%0, %1}, [%2];" : "=l"(sc), "=l"(sd) : "r"(a + 16));
            asm("fma.rn.f32x2 %0, %1, %2, %0;" : "+l"(acc[0]) : "l"(w0pk), "l"(sa));
            asm("fma.rn.f32x2 %0, %1, %2, %0;" : "+l"(acc[1]) : "l"(w0pk), "l"(sb));
            asm("fma.rn.f32x2 %0, %1, %2, %0;" : "+l"(acc[2]) : "l"(w0pk), "l"(sc));
            asm("fma.rn.f32x2 %0, %1, %2, %0;" : "+l"(acc[3]) : "l"(w0pk), "l"(sd));
            asm("fma.rn.f32x2 %0, %1, %2, %0;" : "+l"(acc[4]) : "l"(w1pk), "l"(sa));
            asm("fma.rn.f32x2 %0, %1, %2, %0;" : "+l"(acc[5]) : "l"(w1pk), "l"(sb));
            asm("fma.rn.f32x2 %0, %1, %2, %0;" : "+l"(acc[6]) : "l"(w1pk), "l"(sc));
            asm("fma.rn.f32x2 %0, %1, %2, %0;" : "+l"(acc[7]) : "l"(w1pk), "l"(sd));
        }
        __syncthreads();
    }

    float bias0 = dcn_b[oc0], bias1 = dcn_b[oc0 + 64];
    float* o0 = &g_out1[b][oc0][p0 + pbase];
    float* o1 = &g_out1[b][oc0 + 64][p0 + pbase];
#pragma unroll
    for (int q = 0; q < 2; q++) {
        float e0, e1, e2, e3;
        asm("mov.b64 {%0, %1}, %2;" : "=f"(e0), "=f"(e1) : "l"(acc[2*q]));
        asm("mov.b64 {%0, %1}, %2;" : "=f"(e2), "=f"(e3) : "l"(acc[2*q+1]));
        ((float4*)o0)[q] = make_float4(e0 + bias0, e1 + bias0, e2 + bias0, e3 + bias0);
        asm("mov.b64 {%0, %1}, %2;" : "=f"(e0), "=f"(e1) : "l"(acc[4+2*q]));
        asm("mov.b64 {%0, %1}, %2;" : "=f"(e2), "=f"(e3) : "l"(acc[4+2*q+1]));
        ((float4*)o1)[q] = make_float4(e0 + bias1, e1 + bias1, e2 + bias1, e3 + bias1);
    }
}

// ---------------- BN stats: 2-stage deterministic reduction ----------------
__global__ void bn_partial_kernel(const float* __restrict__ ext, int which) {
    int bx = blockIdx.x;
    int c = bx >> 2, b = bx & 3;
    const float* plane = which ? ext + (size_t)(b * 128 + c) * 16384
                               : &g_out1[b][c][0];
    int n4 = which ? 4096 : 1024;
    float s = 0.f, s2 = 0.f;
    const float4* p4 = (const float4*)plane;
    for (int i = threadIdx.x; i < n4; i += 128) {
        float4 v = p4[i];
        s  += v.x + v.y + v.z + v.w;
        s2 += v.x*v.x + v.y*v.y + v.z*v.z + v.w*v.w;
    }
    __shared__ float rs[128], rq[128];
    rs[threadIdx.x] = s; rq[threadIdx.x] = s2;
    __syncthreads();
    for (int st = 64; st > 0; st >>= 1) {
        if (threadIdx.x < st) {
            rs[threadIdx.x] += rs[threadIdx.x + st];
            rq[threadIdx.x] += rq[threadIdx.x + st];
        }
        __syncthreads();
    }
    if (threadIdx.x == 0) {
        g_psum[which][bx][0] = rs[0];
        g_psum[which][bx][1] = rq[0];
    }
}

__global__ void bn_final_kernel(const float* __restrict__ gamma,
                                const float* __restrict__ beta, int which) {
    int c = threadIdx.x;
    float s = 0.f, s2 = 0.f;
#pragma unroll
    for (int b = 0; b < 4; b++) {
        s  += g_psum[which][c * 4 + b][0];
        s2 += g_psum[which][c * 4 + b][1];
    }
    float n  = which ? 65536.f : 16384.f;
    float mu = s / n;
    float var = s2 / n - mu * mu;
    float sc = gamma[c] * rsqrtf(var + 1e-5f);
    float sh = beta[c] - mu * sc;
    if (which == 0) { g_bn1s[c] = sc; g_bn1b[c] = sh; }
    else            { g_bn2s[c] = sc; g_bn2b[c] = sh; }
}

// ---------------- transposed conv as parity GEMMs (R3-v2, best measured) ----
#define SSP 68
__global__ void __launch_bounds__(128) transp_kernel(float* __restrict__ out) {
    int blk = blockIdx.x;
    int u   = blk & 63;
    int par = (blk >> 6) & 3;
    int b   = blk >> 8;
    int py = par >> 1, px = par & 1;
    int tid = threadIdx.x;

    __shared__ float srow[16 * 2 * 64];              // [ci][t][col], BN1+ReLU applied
    __shared__ __align__(16) float ssam[64 * SSP];   // [ck=ci*4+t*2+s][p]

    int oc0 = tid & 63;
    int pbase = (tid >> 6) << 5;      // 0 or 32

    unsigned long long acc[32];       // [0..15]=oc0, [16..31]=oc0+64
#pragma unroll
    for (int i = 0; i < 32; i++) acc[i] = 0ull;

    unsigned sbase = (unsigned)__cvta_generic_to_shared(ssam);

#pragma unroll 1
    for (int cb = 0; cb < 8; cb++) {                 // 16 channels per chunk
        for (int e = tid; e < 16 * 2 * 16; e += 128) {
            int ci = e >> 5;
            int tt = (e >> 4) & 1;
            int f4 = e & 15;
            int c  = cb * 16 + ci;
            int row = u + py - 1 + tt;
            float4 v = make_float4(0.f, 0.f, 0.f, 0.f);
            if ((unsigned)row < 64u) {
                float4 r = *(const float4*)&g_out1[b][c][row * 64 + f4 * 4];
                float sc = g_bn1s[c], sh = g_bn1b[c];
                v.x = fmaxf(fmaf(r.x, sc, sh), 0.f);
                v.y = fmaxf(fmaf(r.y, sc, sh), 0.f);
                v.z = fmaxf(fmaf(r.z, sc, sh), 0.f);
                v.w = fmaxf(fmaf(r.w, sc, sh), 0.f);
            }
            *(float4*)&srow[(ci * 2 + tt) * 64 + f4 * 4] = v;
        }
        __syncthreads();
        for (int e = tid; e < 64 * 64; e += 128) {
            int ck = e >> 6;
            int p  = e & 63;
            int ci = ck >> 2;
            int tt = (ck >> 1) & 1;
            int s  = ck & 1;
            int col = p + px - 1 + s;
            float v = (col >= 0 && col < 64) ? srow[(ci * 2 + tt) * 64 + col] : 0.f;
            ssam[ck * SSP + p] = v;
        }
        __syncthreads();
#pragma unroll 1
        for (int ts = 0; ts < 4; ts++) {
            int tt = ts >> 1, s = ts & 1;
            int kk = (py + 2 * tt) * 4 + (px + 2 * s);
            const float* wp = g_wT2 + (size_t)kk * 16384 + cb * 16 * 128 + oc0;
            for (int ci = 0; ci < 16; ci++) {
                float wv0 = __ldg(wp + ci * 128);
                float wv1 = __ldg(wp + ci * 128 + 64);
                unsigned long long w0pk, w1pk;
                asm("mov.b64 %0, {%1, %1};" : "=l"(w0pk) : "f"(wv0));
                asm("mov.b64 %0, {%1, %1};" : "=l"(w1pk) : "f"(wv1));
                int ck = ci * 4 + ts;
                unsigned a = sbase + (ck * SSP + pbase) * 4;
#pragma unroll
                for (int q = 0; q < 8; q++) {
                    unsigned long long sa, sb;
                    asm volatile("ld.shared.v2.b64 {%0, %1}, [%2];"
                                 : "=l"(sa), "=l"(sb) : "r"(a + q * 16));
                    asm("fma.rn.f32x2 %0, %1, %2, %0;" : "+l"(acc[2*q])      : "l"(w0pk), "l"(sa));
                    asm("fma.rn.f32x2 %0, %1, %2, %0;" : "+l"(acc[2*q+1])    : "l"(w0pk), "l"(sb));
                    asm("fma.rn.f32x2 %0, %1, %2, %0;" : "+l"(acc[16+2*q])   : "l"(w1pk), "l"(sa));
                    asm("fma.rn.f32x2 %0, %1, %2, %0;" : "+l"(acc[16+2*q+1]) : "l"(w1pk), "l"(sb));
                }
            }
        }
        __syncthreads();
    }

    int y = 2 * u + py;
    float* o0 = out + (((size_t)(b * 128 + oc0)      * 128 + y) * 128) + px + 2 * pbase;
    float* o1 = out + (((size_t)(b * 128 + oc0 + 64) * 128 + y) * 128) + px + 2 * pbase;
#pragma unroll
    for (int q = 0; q < 8; q++) {
        float e0, e1, e2, e3;
        asm("mov.b64 {%0, %1}, %2;" : "=f"(e0), "=f"(e1) : "l"(acc[2*q]));
        asm("mov.b64 {%0, %1}, %2;" : "=f"(e2), "=f"(e3) : "l"(acc[2*q+1]));
        o0[(4*q + 0) * 2] = e0; o0[(4*q + 1) * 2] = e1;
        o0[(4*q + 2) * 2] = e2; o0[(4*q + 3) * 2] = e3;
        asm("mov.b64 {%0, %1}, %2;" : "=f"(e0), "=f"(e1) : "l"(acc[16+2*q]));
        asm("mov.b64 {%0, %1}, %2;" : "=f"(e2), "=f"(e3) : "l"(acc[16+2*q+1]));
        o1[(4*q + 0) * 2] = e0; o1[(4*q + 1) * 2] = e1;
        o1[(4*q + 2) * 2] = e2; o1[(4*q + 3) * 2] = e3;
    }
}

// ---------------- BN2 apply + ReLU, in place on d_out ----------------
__global__ void bn_apply_kernel(float* __restrict__ out) {
    int i = blockIdx.x * 256 + threadIdx.x;
    int c = (i >> 12) & 127;
    float sc = g_bn2s[c], sh = g_bn2b[c];
    float4 v = ((float4*)out)[i];
    v.x = fmaxf(v.x * sc + sh, 0.f);
    v.y = fmaxf(v.y * sc + sh, 0.f);
    v.z = fmaxf(v.z * sc + sh, 0.f);
    v.w = fmaxf(v.w * sc + sh, 0.f);
    ((float4*)out)[i] = v;
}

// ---------------- launch ----------------
extern "C" void kernel_launch(void* const* d_in, const int* in_sizes, int n_in,
                              void* d_out, int out_size) {
    const float* x     = (const float*)d_in[0];
    const float* off_w = (const float*)d_in[1];
    const float* off_b = (const float*)d_in[2];
    const float* dcn_w = (const float*)d_in[3];
    const float* dcn_b = (const float*)d_in[4];
    const float* bn1_g = (const float*)d_in[5];
    const float* bn1_b = (const float*)d_in[6];
    const float* up_w  = (const float*)d_in[7];
    const float* bn2_g = (const float*)d_in[8];
    const float* bn2_b = (const float*)d_in[9];
    float* out = (float*)d_out;

    prep_kernel<<<1152, 256>>>(dcn_w, up_w);
    nhwc_kernel<<<dim3(128, 8, 4), dim3(32, 8)>>>(x);
    offset_conv_kernel<<<256, 512>>>(x, off_w, off_b);
    deform_kernel<<<512, 256>>>(dcn_b);
    bn_partial_kernel<<<512, 128>>>(nullptr, 0);
    bn_final_kernel<<<1, 128>>>(bn1_g, bn1_b, 0);
    transp_kernel<<<1024, 128>>>(out);
    bn_partial_kernel<<<512, 128>>>(out, 1);
    bn_final_kernel<<<1, 128>>>(bn2_g, bn2_b, 1);
    bn_apply_kernel<<<8192, 256>>>(out);
}

// round 10
// speedup vs baseline: 1.2366x; 1.1264x over previous
#include <cuda_runtime.h>
#include <cuda_bf16.h>
#include <cstdint>
#include <math.h>

#define Bsz  4
#define CIN  256
#define COUT 128
#define HW   4096

// ---------------- device scratch ----------------
__device__ float g_xt[Bsz * HW * CIN];        // NHWC x
__device__ float g_off[Bsz][27][HW];
__device__ float g_out1[Bsz][COUT][HW];
__device__ float g_wT2[16 * COUT * COUT];     // transp weights [kk][c][o]
__device__ uint4 g_wAhi[16 * 18 * 8 * 32];    // deform A-fragments (tf32 hi), per-thread float4
__device__ uint4 g_wAlo[16 * 18 * 8 * 32];    // deform A-fragments (tf32 lo)
__device__ float g_bn1s[COUT], g_bn1b[COUT];
__device__ float g_bn2s[COUT], g_bn2b[COUT];
__device__ float g_psum[2][512][2];

__device__ __forceinline__ unsigned f2tf(float f) {
    unsigned u;
    asm("cvt.rna.tf32.f32 %0, %1;" : "=r"(u) : "f"(f));
    return u;
}

// ---------------- weight prep ----------------
__global__ void prep_kernel(const float* __restrict__ dcn_w,
                            const float* __restrict__ up_w) {
    int i = blockIdx.x * blockDim.x + threadIdx.x;
    if (i < 16 * COUT * COUT) {
        int o  = i & 127;
        int c  = (i >> 7) & 127;
        int kk = i >> 14;
        int ky = kk >> 2, kx = kk & 3;
        g_wT2[i] = up_w[((c * COUT + o) * 4 + (3 - ky)) * 4 + (3 - kx)];
    }
    if (i < 73728) {                       // 16 cb * 18 kc * 8 wr * 32 lanes
        int lane = i & 31;
        int wr   = (i >> 5) & 7;
        int ck   = i >> 8;                 // cb*18 + kc
        int kc   = ck % 18;
        int cb   = ck / 18;
        int g    = lane >> 2;
        int tig  = lane & 3;
        int row0 = wr * 16 + g,  row1 = row0 + 8;
        int col0 = kc * 8 + tig, col1 = col0 + 4;
        // W[oc][r] = dcn_w[oc*2304 + (cb*16 + (r&15))*9 + (r>>4)]
        float w0 = dcn_w[row0 * 2304 + (cb * 16 + (col0 & 15)) * 9 + (col0 >> 4)];
        float w1 = dcn_w[row1 * 2304 + (cb * 16 + (col0 & 15)) * 9 + (col0 >> 4)];
        float w2 = dcn_w[row0 * 2304 + (cb * 16 + (col1 & 15)) * 9 + (col1 >> 4)];
        float w3 = dcn_w[row1 * 2304 + (cb * 16 + (col1 & 15)) * 9 + (col1 >> 4)];
        unsigned h0 = f2tf(w0), h1 = f2tf(w1), h2 = f2tf(w2), h3 = f2tf(w3);
        g_wAhi[i] = make_uint4(h0, h1, h2, h3);
        g_wAlo[i] = make_uint4(f2tf(w0 - __uint_as_float(h0)),
                               f2tf(w1 - __uint_as_float(h1)),
                               f2tf(w2 - __uint_as_float(h2)),
                               f2tf(w3 - __uint_as_float(h3)));
    }
}

// ---------------- NCHW -> NHWC transpose of x ----------------
__global__ void nhwc_kernel(const float* __restrict__ x) {
    __shared__ float t[32][33];
    int b  = blockIdx.z;
    int p0 = blockIdx.x * 32;
    int c0 = blockIdx.y * 32;
    int tx = threadIdx.x, ty = threadIdx.y;
#pragma unroll
    for (int i = 0; i < 4; i++)
        t[ty + i * 8][tx] = x[((size_t)(b * CIN + c0 + ty + i * 8)) * HW + p0 + tx];
    __syncthreads();
#pragma unroll
    for (int i = 0; i < 4; i++)
        g_xt[((size_t)(b * HW + p0 + ty + i * 8)) * CIN + c0 + tx] = t[tx][ty + i * 8];
}

// ---------------- offset conv: 3x3, 256 -> 27, pad 1 ----------------
#define OG 8
__global__ void offset_conv_kernel(const float* __restrict__ x,
                                   const float* __restrict__ off_w,
                                   const float* __restrict__ off_b) {
    int bh = blockIdx.x;
    int b = bh >> 6, h = bh & 63;
    int g = threadIdx.x >> 6;
    int w = threadIdx.x & 63;
    __shared__ float srow[OG][3][64];
    __shared__ float sws[OG][324];
    __shared__ float red[OG][64];

    float acc[27];
#pragma unroll
    for (int i = 0; i < 27; i++) acc[i] = 0.f;

    const float* xb = x + (size_t)b * CIN * HW;
    for (int cc = 0; cc < CIN / OG; cc++) {
        int c = g * (CIN / OG) + cc;
#pragma unroll
        for (int r = 0; r < 3; r++) {
            int hh = h + r - 1;
            srow[g][r][w] = (hh >= 0 && hh < 64) ? xb[(size_t)c * HW + hh * 64 + w] : 0.f;
        }
        const float* wc = off_w + c * 9;
        for (int j = w; j < 243; j += 64) {
            int oc = j / 9, tap = j - oc * 9;
            sws[g][oc * 12 + tap] = wc[(size_t)oc * (CIN * 9) + tap];
        }
        __syncthreads();
        float xv[9];
#pragma unroll
        for (int tap = 0; tap < 9; tap++) {
            int col = w + (tap % 3) - 1;
            xv[tap] = (col >= 0 && col < 64) ? srow[g][tap / 3][col] : 0.f;
        }
#pragma unroll
        for (int oc = 0; oc < 27; oc++) {
            const float4* wv = (const float4*)&sws[g][oc * 12];
            float4 w0 = wv[0], w1 = wv[1], w2 = wv[2];
            float a = acc[oc];
            a = fmaf(w0.x, xv[0], a); a = fmaf(w0.y, xv[1], a);
            a = fmaf(w0.z, xv[2], a); a = fmaf(w0.w, xv[3], a);
            a = fmaf(w1.x, xv[4], a); a = fmaf(w1.y, xv[5], a);
            a = fmaf(w1.z, xv[6], a); a = fmaf(w1.w, xv[7], a);
            a = fmaf(w2.x, xv[8], a);
            acc[oc] = a;
        }
        __syncthreads();
    }
    for (int oc = 0; oc < 27; oc++) {
        red[g][w] = acc[oc];
        __syncthreads();
        if (g == 0) {
            float v = red[0][w] + red[1][w] + red[2][w] + red[3][w]
                    + red[4][w] + red[5][w] + red[6][w] + red[7][w] + off_b[oc];
            if (oc >= 18) v = 1.f / (1.f + __expf(-v));
            g_off[b][oc][h * 64 + w] = v;
        }
        __syncthreads();
    }
}

// ---------------- deformable conv: gather + 3xTF32 mma.sync GEMM ----------------
// grid = B*128 (block = 32 px), block = 256 (8 warps; warp = 16 oc x 32 px).
#define SSP2 36
__device__ __forceinline__ void dgather(int tid, int cb, float* sbuf,
                                        const float* __restrict__ xtb,
                                        const int4* sidx, const float4* swt) {
    for (int it = tid; it < 1152; it += 256) {
        int c = it & 15;
        int kp = it >> 4;          // 0..71
        int k = kp >> 3;
        int p4 = kp & 7;
        const float* xc = xtb + cb * 16 + c;
        float4 v;
        float* vp = &v.x;
#pragma unroll
        for (int j = 0; j < 4; j++) {
            int e = k * 32 + p4 * 4 + j;
            int4 id = sidx[e];
            float4 wt = swt[e];
            float r =      wt.x * __ldg(xc + id.x * CIN);
            r = fmaf(wt.y, __ldg(xc + id.y * CIN), r);
            r = fmaf(wt.z, __ldg(xc + id.z * CIN), r);
            r = fmaf(wt.w, __ldg(xc + id.w * CIN), r);
            vp[j] = r;
        }
        *(float4*)&sbuf[(k * 16 + c) * SSP2 + p4 * 4] = v;
    }
}

#define MMA_TF32(d, a, b0, b1) \
    asm volatile("mma.sync.aligned.m16n8k8.row.col.f32.tf32.tf32.f32 " \
        "{%0,%1,%2,%3}, {%4,%5,%6,%7}, {%8,%9}, {%0,%1,%2,%3};" \
        : "+f"((d)[0]), "+f"((d)[1]), "+f"((d)[2]), "+f"((d)[3]) \
        : "r"((a).x), "r"((a).y), "r"((a).z), "r"((a).w), "r"(b0), "r"(b1))

__global__ void __launch_bounds__(256) deform_kernel(const float* __restrict__ dcn_b) {
    int blk = blockIdx.x;
    int b = blk >> 7;
    int t = blk & 127;
    int h = t >> 1;
    int w0 = (t & 1) << 5;
    int p0 = h * 64 + w0;
    int tid = threadIdx.x;
    int lane = tid & 31, wid = tid >> 5;

    __shared__ int4  sidx[288];
    __shared__ float4 swt[288];
    __shared__ __align__(16) float ssam[2][144 * SSP2];

    for (int e = tid; e < 288; e += 256) {
        int k = e >> 5, p = e & 31;
        float dy = g_off[b][k][p0 + p];
        float dx = g_off[b][9 + k][p0 + p];
        float m  = g_off[b][18 + k][p0 + p];
        float py = dy + (float)(k / 3 - 1 + h);
        float px = dx + (float)(k % 3 - 1 + w0 + p);
        float y0f = floorf(py), x0f = floorf(px);
        int y0 = (int)y0f, x0i = (int)x0f;
        float wy = py - y0f, wx = px - x0f;
        float w00 = (1.f - wy) * (1.f - wx) * m;
        float w01 = (1.f - wy) * wx * m;
        float w10 = wy * (1.f - wx) * m;
        float w11 = wy * wx * m;
        int y1 = y0 + 1, x1i = x0i + 1;
        bool y0v = (unsigned)y0  < 64u, y1v = (unsigned)y1  < 64u;
        bool x0v = (unsigned)x0i < 64u, x1v = (unsigned)x1i < 64u;
        int y0c = min(max(y0, 0), 63),  y1c = min(max(y1, 0), 63);
        int x0c = min(max(x0i, 0), 63), x1c = min(max(x1i, 0), 63);
        sidx[e] = make_int4(y0c * 64 + x0c, y0c * 64 + x1c,
                            y1c * 64 + x0c, y1c * 64 + x1c);
        swt[e] = make_float4(y0v && x0v ? w00 : 0.f,
                             y0v && x1v ? w01 : 0.f,
                             y1v && x0v ? w10 : 0.f,
                             y1v && x1v ? w11 : 0.f);
    }
    __syncthreads();

    int g   = lane >> 2;       // 0..7
    int tig = lane & 3;        // 0..3

    float d[4][4];             // 4 n-tiles x 4 accum regs
#pragma unroll
    for (int i = 0; i < 4; i++)
#pragma unroll
        for (int j = 0; j < 4; j++) d[i][j] = 0.f;

    unsigned sbase = (unsigned)__cvta_generic_to_shared(&ssam[0][0]);
    const float* xtb = g_xt + (size_t)b * HW * CIN;

    dgather(tid, 0, &ssam[0][0], xtb, sidx, swt);
    __syncthreads();

#pragma unroll 1
    for (int cb = 0; cb < 16; cb++) {
        if (cb < 15) dgather(tid, cb + 1, &ssam[(cb + 1) & 1][0], xtb, sidx, swt);
        const uint4* ph = g_wAhi + ((cb * 18) * 8 + wid) * 32 + lane;
        const uint4* pl = g_wAlo + ((cb * 18) * 8 + wid) * 32 + lane;
        unsigned sb = sbase + (cb & 1) * (144 * SSP2 * 4);
#pragma unroll 2
        for (int kc = 0; kc < 18; kc++) {
            uint4 ah = __ldg(ph + kc * 256);
            uint4 al = __ldg(pl + kc * 256);
            unsigned base0 = sb + ((kc * 8 + tig) * SSP2 + g) * 4;
            unsigned base1 = base0 + 4 * SSP2 * 4;
#pragma unroll
            for (int nt = 0; nt < 4; nt++) {
                float s0, s1;
                asm volatile("ld.shared.f32 %0, [%1];" : "=f"(s0) : "r"(base0 + nt * 32));
                asm volatile("ld.shared.f32 %0, [%1];" : "=f"(s1) : "r"(base1 + nt * 32));
                unsigned bh0 = f2tf(s0), bh1 = f2tf(s1);
                unsigned bl0 = f2tf(s0 - __uint_as_float(bh0));
                unsigned bl1 = f2tf(s1 - __uint_as_float(bh1));
                MMA_TF32(d[nt], ah, bh0, bh1);
                MMA_TF32(d[nt], al, bh0, bh1);
                MMA_TF32(d[nt], ah, bl0, bl1);
            }
        }
        __syncthreads();
    }

    int oc0 = wid * 16 + g;
    float bias0 = dcn_b[oc0], bias1 = dcn_b[oc0 + 8];
    float* r0 = &g_out1[b][oc0][p0];
    float* r1 = &g_out1[b][oc0 + 8][p0];
#pragma unroll
    for (int nt = 0; nt < 4; nt++) {
        int col = nt * 8 + 2 * tig;
        *(float2*)(r0 + col) = make_float2(d[nt][0] + bias0, d[nt][1] + bias0);
        *(float2*)(r1 + col) = make_float2(d[nt][2] + bias1, d[nt][3] + bias1);
    }
}

// ---------------- BN stats ----------------
__global__ void bn_partial_kernel(const float* __restrict__ ext, int which) {
    int bx = blockIdx.x;
    int c = bx >> 2, b = bx & 3;
    const float* plane = which ? ext + (size_t)(b * 128 + c) * 16384
                               : &g_out1[b][c][0];
    int n4 = which ? 4096 : 1024;
    float s = 0.f, s2 = 0.f;
    const float4* p4 = (const float4*)plane;
    for (int i = threadIdx.x; i < n4; i += 128) {
        float4 v = p4[i];
        s  += v.x + v.y + v.z + v.w;
        s2 += v.x*v.x + v.y*v.y + v.z*v.z + v.w*v.w;
    }
    __shared__ float rs[128], rq[128];
    rs[threadIdx.x] = s; rq[threadIdx.x] = s2;
    __syncthreads();
    for (int st = 64; st > 0; st >>= 1) {
        if (threadIdx.x < st) {
            rs[threadIdx.x] += rs[threadIdx.x + st];
            rq[threadIdx.x] += rq[threadIdx.x + st];
        }
        __syncthreads();
    }
    if (threadIdx.x == 0) {
        g_psum[which][bx][0] = rs[0];
        g_psum[which][bx][1] = rq[0];
    }
}

__global__ void bn_final_kernel(const float* __restrict__ gamma,
                                const float* __restrict__ beta, int which) {
    int c = threadIdx.x;
    float s = 0.f, s2 = 0.f;
#pragma unroll
    for (int b = 0; b < 4; b++) {
        s  += g_psum[which][c * 4 + b][0];
        s2 += g_psum[which][c * 4 + b][1];
    }
    float n  = which ? 65536.f : 16384.f;
    float mu = s / n;
    float var = s2 / n - mu * mu;
    float sc = gamma[c] * rsqrtf(var + 1e-5f);
    float sh = beta[c] - mu * sc;
    if (which == 0) { g_bn1s[c] = sc; g_bn1b[c] = sh; }
    else            { g_bn2s[c] = sc; g_bn2b[c] = sh; }
}

// ---------------- transposed conv (R3-v2) ----------------
#define SSP 68
__global__ void __launch_bounds__(128) transp_kernel(float* __restrict__ out) {
    int blk = blockIdx.x;
    int u   = blk & 63;
    int par = (blk >> 6) & 3;
    int b   = blk >> 8;
    int py = par >> 1, px = par & 1;
    int tid = threadIdx.x;

    __shared__ float srow[16 * 2 * 64];
    __shared__ __align__(16) float ssam[64 * SSP];

    int oc0 = tid & 63;
    int pbase = (tid >> 6) << 5;

    unsigned long long acc[32];
#pragma unroll
    for (int i = 0; i < 32; i++) acc[i] = 0ull;

    unsigned sbase = (unsigned)__cvta_generic_to_shared(ssam);

#pragma unroll 1
    for (int cb = 0; cb < 8; cb++) {
        for (int e = tid; e < 16 * 2 * 16; e += 128) {
            int ci = e >> 5;
            int tt = (e >> 4) & 1;
            int f4 = e & 15;
            int c  = cb * 16 + ci;
            int row = u + py - 1 + tt;
            float4 v = make_float4(0.f, 0.f, 0.f, 0.f);
            if ((unsigned)row < 64u) {
                float4 r = *(const float4*)&g_out1[b][c][row * 64 + f4 * 4];
                float sc = g_bn1s[c], sh = g_bn1b[c];
                v.x = fmaxf(fmaf(r.x, sc, sh), 0.f);
                v.y = fmaxf(fmaf(r.y, sc, sh), 0.f);
                v.z = fmaxf(fmaf(r.z, sc, sh), 0.f);
                v.w = fmaxf(fmaf(r.w, sc, sh), 0.f);
            }
            *(float4*)&srow[(ci * 2 + tt) * 64 + f4 * 4] = v;
        }
        __syncthreads();
        for (int e = tid; e < 64 * 64; e += 128) {
            int ck = e >> 6;
            int p  = e & 63;
            int ci = ck >> 2;
            int tt = (ck >> 1) & 1;
            int s  = ck & 1;
            int col = p + px - 1 + s;
            float v = (col >= 0 && col < 64) ? srow[(ci * 2 + tt) * 64 + col] : 0.f;
            ssam[ck * SSP + p] = v;
        }
        __syncthreads();
#pragma unroll 1
        for (int ts = 0; ts < 4; ts++) {
            int tt = ts >> 1, s = ts & 1;
            int kk = (py + 2 * tt) * 4 + (px + 2 * s);
            const float* wp = g_wT2 + (size_t)kk * 16384 + cb * 16 * 128 + oc0;
            for (int ci = 0; ci < 16; ci++) {
                float wv0 = __ldg(wp + ci * 128);
                float wv1 = __ldg(wp + ci * 128 + 64);
                unsigned long long w0pk, w1pk;
                asm("mov.b64 %0, {%1, %1};" : "=l"(w0pk) : "f"(wv0));
                asm("mov.b64 %0, {%1, %1};" : "=l"(w1pk) : "f"(wv1));
                int ck = ci * 4 + ts;
                unsigned a = sbase + (ck * SSP + pbase) * 4;
#pragma unroll
                for (int q = 0; q < 8; q++) {
                    unsigned long long sa, sb;
                    asm volatile("ld.shared.v2.b64 {%0, %1}, [%2];"
                                 : "=l"(sa), "=l"(sb) : "r"(a + q * 16));
                    asm("fma.rn.f32x2 %0, %1, %2, %0;" : "+l"(acc[2*q])      : "l"(w0pk), "l"(sa));
                    asm("fma.rn.f32x2 %0, %1, %2, %0;" : "+l"(acc[2*q+1])    : "l"(w0pk), "l"(sb));
                    asm("fma.rn.f32x2 %0, %1, %2, %0;" : "+l"(acc[16+2*q])   : "l"(w1pk), "l"(sa));
                    asm("fma.rn.f32x2 %0, %1, %2, %0;" : "+l"(acc[16+2*q+1]) : "l"(w1pk), "l"(sb));
                }
            }
        }
        __syncthreads();
    }

    int y = 2 * u + py;
    float* o0 = out + (((size_t)(b * 128 + oc0)      * 128 + y) * 128) + px + 2 * pbase;
    float* o1 = out + (((size_t)(b * 128 + oc0 + 64) * 128 + y) * 128) + px + 2 * pbase;
#pragma unroll
    for (int q = 0; q < 8; q++) {
        float e0, e1, e2, e3;
        asm("mov.b64 {%0, %1}, %2;" : "=f"(e0), "=f"(e1) : "l"(acc[2*q]));
        asm("mov.b64 {%0, %1}, %2;" : "=f"(e2), "=f"(e3) : "l"(acc[2*q+1]));
        o0[(4*q + 0) * 2] = e0; o0[(4*q + 1) * 2] = e1;
        o0[(4*q + 2) * 2] = e2; o0[(4*q + 3) * 2] = e3;
        asm("mov.b64 {%0, %1}, %2;" : "=f"(e0), "=f"(e1) : "l"(acc[16+2*q]));
        asm("mov.b64 {%0, %1}, %2;" : "=f"(e2), "=f"(e3) : "l"(acc[16+2*q+1]));
        o1[(4*q + 0) * 2] = e0; o1[(4*q + 1) * 2] = e1;
        o1[(4*q + 2) * 2] = e2; o1[(4*q + 3) * 2] = e3;
    }
}

// ---------------- BN2 apply + ReLU ----------------
__global__ void bn_apply_kernel(float* __restrict__ out) {
    int i = blockIdx.x * 256 + threadIdx.x;
    int c = (i >> 12) & 127;
    float sc = g_bn2s[c], sh = g_bn2b[c];
    float4 v = ((float4*)out)[i];
    v.x = fmaxf(v.x * sc + sh, 0.f);
    v.y = fmaxf(v.y * sc + sh, 0.f);
    v.z = fmaxf(v.z * sc + sh, 0.f);
    v.w = fmaxf(v.w * sc + sh, 0.f);
    ((float4*)out)[i] = v;
}

// ---------------- launch ----------------
extern "C" void kernel_launch(void* const* d_in, const int* in_sizes, int n_in,
                              void* d_out, int out_size) {
    const float* x     = (const float*)d_in[0];
    const float* off_w = (const float*)d_in[1];
    const float* off_b = (const float*)d_in[2];
    const float* dcn_w = (const float*)d_in[3];
    const float* dcn_b = (const float*)d_in[4];
    const float* bn1_g = (const float*)d_in[5];
    const float* bn1_b = (const float*)d_in[6];
    const float* up_w  = (const float*)d_in[7];
    const float* bn2_g = (const float*)d_in[8];
    const float* bn2_b = (const float*)d_in[9];
    float* out = (float*)d_out;

    prep_kernel<<<1152, 256>>>(dcn_w, up_w);
    nhwc_kernel<<<dim3(128, 8, 4), dim3(32, 8)>>>(x);
    offset_conv_kernel<<<256, 512>>>(x, off_w, off_b);
    deform_kernel<<<512, 256>>>(dcn_b);
    bn_partial_kernel<<<512, 128>>>(nullptr, 0);
    bn_final_kernel<<<1, 128>>>(bn1_g, bn1_b, 0);
    transp_kernel<<<1024, 128>>>(out);
    bn_partial_kernel<<<512, 128>>>(out, 1);
    bn_final_kernel<<<1, 128>>>(bn2_g, bn2_b, 1);
    bn_apply_kernel<<<8192, 256>>>(out);
}

// round 11
// speedup vs baseline: 1.3343x; 1.0791x over previous
#include <cuda_runtime.h>
#include <cuda_bf16.h>
#include <cstdint>
#include <math.h>

#define Bsz  4
#define CIN  256
#define COUT 128
#define HW   4096

// ---------------- device scratch ----------------
__device__ float g_xt[Bsz * HW * CIN];        // NHWC x
__device__ float g_off[Bsz][27][HW];
__device__ float g_out1[Bsz][COUT][HW];
__device__ uint4 g_wAhi[16 * 18 * 8 * 32];    // deform A-fragments (tf32 hi)
__device__ uint4 g_wAlo[16 * 18 * 8 * 32];    // deform A-fragments (tf32 lo)
__device__ uint4 g_wBhi[4 * 8 * 8 * 8 * 32];  // transp A-fragments per parity (tf32 hi)
__device__ uint4 g_wBlo[4 * 8 * 8 * 8 * 32];  // transp A-fragments per parity (tf32 lo)
__device__ float g_bn1s[COUT], g_bn1b[COUT];
__device__ float g_bn2s[COUT], g_bn2b[COUT];
__device__ float g_psum[2][512][2];

__device__ __forceinline__ unsigned f2tf(float f) {
    unsigned u;
    asm("cvt.rna.tf32.f32 %0, %1;" : "=r"(u) : "f"(f));
    return u;
}

// ---------------- weight prep ----------------
__global__ void prep_kernel(const float* __restrict__ dcn_w,
                            const float* __restrict__ up_w) {
    int i = blockIdx.x * blockDim.x + threadIdx.x;
    if (i < 73728) {                       // deform: 16 cb * 18 kc * 8 wr * 32 lanes
        int lane = i & 31;
        int wr   = (i >> 5) & 7;
        int ck   = i >> 8;
        int kc   = ck % 18;
        int cb   = ck / 18;
        int g    = lane >> 2;
        int tig  = lane & 3;
        int row0 = wr * 16 + g,  row1 = row0 + 8;
        int col0 = kc * 8 + tig, col1 = col0 + 4;
        float w0 = dcn_w[row0 * 2304 + (cb * 16 + (col0 & 15)) * 9 + (col0 >> 4)];
        float w1 = dcn_w[row1 * 2304 + (cb * 16 + (col0 & 15)) * 9 + (col0 >> 4)];
        float w2 = dcn_w[row0 * 2304 + (cb * 16 + (col1 & 15)) * 9 + (col1 >> 4)];
        float w3 = dcn_w[row1 * 2304 + (cb * 16 + (col1 & 15)) * 9 + (col1 >> 4)];
        unsigned h0 = f2tf(w0), h1 = f2tf(w1), h2 = f2tf(w2), h3 = f2tf(w3);
        g_wAhi[i] = make_uint4(h0, h1, h2, h3);
        g_wAlo[i] = make_uint4(f2tf(w0 - __uint_as_float(h0)),
                               f2tf(w1 - __uint_as_float(h1)),
                               f2tf(w2 - __uint_as_float(h2)),
                               f2tf(w3 - __uint_as_float(h3)));
    }
    if (i < 65536) {                       // transp: 4 par * 8 cb * 8 kc * 8 wr * 32 lanes
        int lane = i & 31;
        int wr   = (i >> 5) & 7;
        int kc   = (i >> 8) & 7;
        int cb   = (i >> 11) & 7;
        int par  = i >> 14;
        int py = par >> 1, px = par & 1;
        int g = lane >> 2, tig = lane & 3;
        int row0 = wr * 16 + g, row1 = row0 + 8;
        int col0 = kc * 8 + tig, col1 = col0 + 4;
        auto wval = [&](int row, int col) -> float {
            int ci = col >> 2, ts = col & 3;
            int t = ts >> 1, s = ts & 1;
            int ch = cb * 16 + ci;
            int ky = py + 2 * t, kx = px + 2 * s;
            return up_w[((ch * 128 + row) * 4 + (3 - ky)) * 4 + (3 - kx)];
        };
        float w0 = wval(row0, col0), w1 = wval(row1, col0);
        float w2 = wval(row0, col1), w3 = wval(row1, col1);
        unsigned h0 = f2tf(w0), h1 = f2tf(w1), h2 = f2tf(w2), h3 = f2tf(w3);
        g_wBhi[i] = make_uint4(h0, h1, h2, h3);
        g_wBlo[i] = make_uint4(f2tf(w0 - __uint_as_float(h0)),
                               f2tf(w1 - __uint_as_float(h1)),
                               f2tf(w2 - __uint_as_float(h2)),
                               f2tf(w3 - __uint_as_float(h3)));
    }
}

// ---------------- NCHW -> NHWC transpose of x ----------------
__global__ void nhwc_kernel(const float* __restrict__ x) {
    __shared__ float t[32][33];
    int b  = blockIdx.z;
    int p0 = blockIdx.x * 32;
    int c0 = blockIdx.y * 32;
    int tx = threadIdx.x, ty = threadIdx.y;
#pragma unroll
    for (int i = 0; i < 4; i++)
        t[ty + i * 8][tx] = x[((size_t)(b * CIN + c0 + ty + i * 8)) * HW + p0 + tx];
    __syncthreads();
#pragma unroll
    for (int i = 0; i < 4; i++)
        g_xt[((size_t)(b * HW + p0 + ty + i * 8)) * CIN + c0 + tx] = t[tx][ty + i * 8];
}

// ---------------- offset conv: 3x3, 256 -> 27, pad 1 ----------------
#define OG 8
__global__ void offset_conv_kernel(const float* __restrict__ x,
                                   const float* __restrict__ off_w,
                                   const float* __restrict__ off_b) {
    int bh = blockIdx.x;
    int b = bh >> 6, h = bh & 63;
    int g = threadIdx.x >> 6;
    int w = threadIdx.x & 63;
    __shared__ float srow[OG][3][64];
    __shared__ float sws[OG][324];
    __shared__ float red[OG][64];

    float acc[27];
#pragma unroll
    for (int i = 0; i < 27; i++) acc[i] = 0.f;

    const float* xb = x + (size_t)b * CIN * HW;
    for (int cc = 0; cc < CIN / OG; cc++) {
        int c = g * (CIN / OG) + cc;
#pragma unroll
        for (int r = 0; r < 3; r++) {
            int hh = h + r - 1;
            srow[g][r][w] = (hh >= 0 && hh < 64) ? xb[(size_t)c * HW + hh * 64 + w] : 0.f;
        }
        const float* wc = off_w + c * 9;
        for (int j = w; j < 243; j += 64) {
            int oc = j / 9, tap = j - oc * 9;
            sws[g][oc * 12 + tap] = wc[(size_t)oc * (CIN * 9) + tap];
        }
        __syncthreads();
        float xv[9];
#pragma unroll
        for (int tap = 0; tap < 9; tap++) {
            int col = w + (tap % 3) - 1;
            xv[tap] = (col >= 0 && col < 64) ? srow[g][tap / 3][col] : 0.f;
        }
#pragma unroll
        for (int oc = 0; oc < 27; oc++) {
            const float4* wv = (const float4*)&sws[g][oc * 12];
            float4 w0 = wv[0], w1 = wv[1], w2 = wv[2];
            float a = acc[oc];
            a = fmaf(w0.x, xv[0], a); a = fmaf(w0.y, xv[1], a);
            a = fmaf(w0.z, xv[2], a); a = fmaf(w0.w, xv[3], a);
            a = fmaf(w1.x, xv[4], a); a = fmaf(w1.y, xv[5], a);
            a = fmaf(w1.z, xv[6], a); a = fmaf(w1.w, xv[7], a);
            a = fmaf(w2.x, xv[8], a);
            acc[oc] = a;
        }
        __syncthreads();
    }
    for (int oc = 0; oc < 27; oc++) {
        red[g][w] = acc[oc];
        __syncthreads();
        if (g == 0) {
            float v = red[0][w] + red[1][w] + red[2][w] + red[3][w]
                    + red[4][w] + red[5][w] + red[6][w] + red[7][w] + off_b[oc];
            if (oc >= 18) v = 1.f / (1.f + __expf(-v));
            g_off[b][oc][h * 64 + w] = v;
        }
        __syncthreads();
    }
}

// ---------------- deformable conv: gather + 3xTF32 mma.sync (R10, proven) ---
#define SSP2 36
__device__ __forceinline__ void dgather(int tid, int cb, float* sbuf,
                                        const float* __restrict__ xtb,
                                        const int4* sidx, const float4* swt) {
    for (int it = tid; it < 1152; it += 256) {
        int c = it & 15;
        int kp = it >> 4;
        int k = kp >> 3;
        int p4 = kp & 7;
        const float* xc = xtb + cb * 16 + c;
        float4 v;
        float* vp = &v.x;
#pragma unroll
        for (int j = 0; j < 4; j++) {
            int e = k * 32 + p4 * 4 + j;
            int4 id = sidx[e];
            float4 wt = swt[e];
            float r =      wt.x * __ldg(xc + id.x * CIN);
            r = fmaf(wt.y, __ldg(xc + id.y * CIN), r);
            r = fmaf(wt.z, __ldg(xc + id.z * CIN), r);
            r = fmaf(wt.w, __ldg(xc + id.w * CIN), r);
            vp[j] = r;
        }
        *(float4*)&sbuf[(k * 16 + c) * SSP2 + p4 * 4] = v;
    }
}

#define MMA_TF32(d, a, b0, b1) \
    asm volatile("mma.sync.aligned.m16n8k8.row.col.f32.tf32.tf32.f32 " \
        "{%0,%1,%2,%3}, {%4,%5,%6,%7}, {%8,%9}, {%0,%1,%2,%3};" \
        : "+f"((d)[0]), "+f"((d)[1]), "+f"((d)[2]), "+f"((d)[3]) \
        : "r"((a).x), "r"((a).y), "r"((a).z), "r"((a).w), "r"(b0), "r"(b1))

__global__ void __launch_bounds__(256) deform_kernel(const float* __restrict__ dcn_b) {
    int blk = blockIdx.x;
    int b = blk >> 7;
    int t = blk & 127;
    int h = t >> 1;
    int w0 = (t & 1) << 5;
    int p0 = h * 64 + w0;
    int tid = threadIdx.x;
    int lane = tid & 31, wid = tid >> 5;

    __shared__ int4  sidx[288];
    __shared__ float4 swt[288];
    __shared__ __align__(16) float ssam[2][144 * SSP2];

    for (int e = tid; e < 288; e += 256) {
        int k = e >> 5, p = e & 31;
        float dy = g_off[b][k][p0 + p];
        float dx = g_off[b][9 + k][p0 + p];
        float m  = g_off[b][18 + k][p0 + p];
        float py = dy + (float)(k / 3 - 1 + h);
        float px = dx + (float)(k % 3 - 1 + w0 + p);
        float y0f = floorf(py), x0f = floorf(px);
        int y0 = (int)y0f, x0i = (int)x0f;
        float wy = py - y0f, wx = px - x0f;
        float w00 = (1.f - wy) * (1.f - wx) * m;
        float w01 = (1.f - wy) * wx * m;
        float w10 = wy * (1.f - wx) * m;
        float w11 = wy * wx * m;
        int y1 = y0 + 1, x1i = x0i + 1;
        bool y0v = (unsigned)y0  < 64u, y1v = (unsigned)y1  < 64u;
        bool x0v = (unsigned)x0i < 64u, x1v = (unsigned)x1i < 64u;
        int y0c = min(max(y0, 0), 63),  y1c = min(max(y1, 0), 63);
        int x0c = min(max(x0i, 0), 63), x1c = min(max(x1i, 0), 63);
        sidx[e] = make_int4(y0c * 64 + x0c, y0c * 64 + x1c,
                            y1c * 64 + x0c, y1c * 64 + x1c);
        swt[e] = make_float4(y0v && x0v ? w00 : 0.f,
                             y0v && x1v ? w01 : 0.f,
                             y1v && x0v ? w10 : 0.f,
                             y1v && x1v ? w11 : 0.f);
    }
    __syncthreads();

    int g   = lane >> 2;
    int tig = lane & 3;

    float d[4][4];
#pragma unroll
    for (int i = 0; i < 4; i++)
#pragma unroll
        for (int j = 0; j < 4; j++) d[i][j] = 0.f;

    unsigned sbase = (unsigned)__cvta_generic_to_shared(&ssam[0][0]);
    const float* xtb = g_xt + (size_t)b * HW * CIN;

    dgather(tid, 0, &ssam[0][0], xtb, sidx, swt);
    __syncthreads();

#pragma unroll 1
    for (int cb = 0; cb < 16; cb++) {
        if (cb < 15) dgather(tid, cb + 1, &ssam[(cb + 1) & 1][0], xtb, sidx, swt);
        const uint4* ph = g_wAhi + ((cb * 18) * 8 + wid) * 32 + lane;
        const uint4* pl = g_wAlo + ((cb * 18) * 8 + wid) * 32 + lane;
        unsigned sb = sbase + (cb & 1) * (144 * SSP2 * 4);
#pragma unroll 2
        for (int kc = 0; kc < 18; kc++) {
            uint4 ah = __ldg(ph + kc * 256);
            uint4 al = __ldg(pl + kc * 256);
            unsigned base0 = sb + ((kc * 8 + tig) * SSP2 + g) * 4;
            unsigned base1 = base0 + 4 * SSP2 * 4;
#pragma unroll
            for (int nt = 0; nt < 4; nt++) {
                float s0, s1;
                asm volatile("ld.shared.f32 %0, [%1];" : "=f"(s0) : "r"(base0 + nt * 32));
                asm volatile("ld.shared.f32 %0, [%1];" : "=f"(s1) : "r"(base1 + nt * 32));
                unsigned bh0 = f2tf(s0), bh1 = f2tf(s1);
                unsigned bl0 = f2tf(s0 - __uint_as_float(bh0));
                unsigned bl1 = f2tf(s1 - __uint_as_float(bh1));
                MMA_TF32(d[nt], ah, bh0, bh1);
                MMA_TF32(d[nt], al, bh0, bh1);
                MMA_TF32(d[nt], ah, bl0, bl1);
            }
        }
        __syncthreads();
    }

    int oc0 = wid * 16 + g;
    float bias0 = dcn_b[oc0], bias1 = dcn_b[oc0 + 8];
    float* r0 = &g_out1[b][oc0][p0];
    float* r1 = &g_out1[b][oc0 + 8][p0];
#pragma unroll
    for (int nt = 0; nt < 4; nt++) {
        int col = nt * 8 + 2 * tig;
        *(float2*)(r0 + col) = make_float2(d[nt][0] + bias0, d[nt][1] + bias0);
        *(float2*)(r1 + col) = make_float2(d[nt][2] + bias1, d[nt][3] + bias1);
    }
}

// ---------------- BN stats ----------------
__global__ void bn_partial_kernel(const float* __restrict__ ext, int which) {
    int bx = blockIdx.x;
    int c = bx >> 2, b = bx & 3;
    const float* plane = which ? ext + (size_t)(b * 128 + c) * 16384
                               : &g_out1[b][c][0];
    int n4 = which ? 4096 : 1024;
    float s = 0.f, s2 = 0.f;
    const float4* p4 = (const float4*)plane;
    for (int i = threadIdx.x; i < n4; i += 128) {
        float4 v = p4[i];
        s  += v.x + v.y + v.z + v.w;
        s2 += v.x*v.x + v.y*v.y + v.z*v.z + v.w*v.w;
    }
    __shared__ float rs[128], rq[128];
    rs[threadIdx.x] = s; rq[threadIdx.x] = s2;
    __syncthreads();
    for (int st = 64; st > 0; st >>= 1) {
        if (threadIdx.x < st) {
            rs[threadIdx.x] += rs[threadIdx.x + st];
            rq[threadIdx.x] += rq[threadIdx.x + st];
        }
        __syncthreads();
    }
    if (threadIdx.x == 0) {
        g_psum[which][bx][0] = rs[0];
        g_psum[which][bx][1] = rq[0];
    }
}

__global__ void bn_final_kernel(const float* __restrict__ gamma,
                                const float* __restrict__ beta, int which) {
    int c = threadIdx.x;
    float s = 0.f, s2 = 0.f;
#pragma unroll
    for (int b = 0; b < 4; b++) {
        s  += g_psum[which][c * 4 + b][0];
        s2 += g_psum[which][c * 4 + b][1];
    }
    float n  = which ? 65536.f : 16384.f;
    float mu = s / n;
    float var = s2 / n - mu * mu;
    float sc = gamma[c] * rsqrtf(var + 1e-5f);
    float sh = beta[c] - mu * sc;
    if (which == 0) { g_bn1s[c] = sc; g_bn1b[c] = sh; }
    else            { g_bn2s[c] = sc; g_bn2b[c] = sh; }
}

// ---------------- transposed conv via 3xTF32 mma.sync ----------------
// grid = 1024 (b,par,u); block = 256 (8 warps; warp = 16 oc x 64 px), K=512/parity.
#define SSP 68
__global__ void __launch_bounds__(256) transp_kernel(float* __restrict__ out) {
    int blk = blockIdx.x;
    int u   = blk & 63;
    int par = (blk >> 6) & 3;
    int b   = blk >> 8;
    int py = par >> 1, px = par & 1;
    int tid = threadIdx.x;
    int lane = tid & 31, wid = tid >> 5;

    __shared__ float srow[16 * 2 * 64];
    __shared__ __align__(16) float ssam[64 * SSP];

    int g = lane >> 2, tig = lane & 3;

    float d[8][4];
#pragma unroll
    for (int i = 0; i < 8; i++)
#pragma unroll
        for (int j = 0; j < 4; j++) d[i][j] = 0.f;

    unsigned sbase = (unsigned)__cvta_generic_to_shared(ssam);

#pragma unroll 1
    for (int cb = 0; cb < 8; cb++) {
        // stage with fused BN1 + ReLU
        for (int e = tid; e < 512; e += 256) {
            int ci = e >> 5;
            int tt = (e >> 4) & 1;
            int f4 = e & 15;
            int c  = cb * 16 + ci;
            int row = u + py - 1 + tt;
            float4 v = make_float4(0.f, 0.f, 0.f, 0.f);
            if ((unsigned)row < 64u) {
                float4 r = *(const float4*)&g_out1[b][c][row * 64 + f4 * 4];
                float sc = g_bn1s[c], sh = g_bn1b[c];
                v.x = fmaxf(fmaf(r.x, sc, sh), 0.f);
                v.y = fmaxf(fmaf(r.y, sc, sh), 0.f);
                v.z = fmaxf(fmaf(r.z, sc, sh), 0.f);
                v.w = fmaxf(fmaf(r.w, sc, sh), 0.f);
            }
            *(float4*)&srow[(ci * 2 + tt) * 64 + f4 * 4] = v;
        }
        __syncthreads();
        // expand to ssam[ck][p] with column shift px-1+s
        for (int e = tid; e < 4096; e += 256) {
            int ck = e >> 6;
            int p  = e & 63;
            int ci = ck >> 2;
            int tt = (ck >> 1) & 1;
            int s  = ck & 1;
            int col = p + px - 1 + s;
            float v = (col >= 0 && col < 64) ? srow[(ci * 2 + tt) * 64 + col] : 0.f;
            ssam[ck * SSP + p] = v;
        }
        __syncthreads();
        // GEMM over 64 ck (8 k-frags)
        const uint4* ph = g_wBhi + (((par * 8 + cb) * 8) * 8 + wid) * 32 + lane;
        const uint4* pl = g_wBlo + (((par * 8 + cb) * 8) * 8 + wid) * 32 + lane;
#pragma unroll 2
        for (int kc = 0; kc < 8; kc++) {
            uint4 ah = __ldg(ph + kc * 256);
            uint4 al = __ldg(pl + kc * 256);
            unsigned base0 = sbase + ((kc * 8 + tig) * SSP + g) * 4;
            unsigned base1 = base0 + 4 * SSP * 4;
#pragma unroll
            for (int nt = 0; nt < 8; nt++) {
                float s0, s1;
                asm volatile("ld.shared.f32 %0, [%1];" : "=f"(s0) : "r"(base0 + nt * 32));
                asm volatile("ld.shared.f32 %0, [%1];" : "=f"(s1) : "r"(base1 + nt * 32));
                unsigned bh0 = f2tf(s0), bh1 = f2tf(s1);
                unsigned bl0 = f2tf(s0 - __uint_as_float(bh0));
                unsigned bl1 = f2tf(s1 - __uint_as_float(bh1));
                MMA_TF32(d[nt], ah, bh0, bh1);
                MMA_TF32(d[nt], al, bh0, bh1);
                MMA_TF32(d[nt], ah, bl0, bl1);
            }
        }
        __syncthreads();
    }

    int y = 2 * u + py;
    int oc0 = wid * 16 + g;
    float* r0 = out + (((size_t)(b * 128 + oc0)     * 128 + y) * 128) + px;
    float* r1 = out + (((size_t)(b * 128 + oc0 + 8) * 128 + y) * 128) + px;
#pragma unroll
    for (int nt = 0; nt < 8; nt++) {
        int p = nt * 8 + 2 * tig;
        r0[2 * p]       = d[nt][0];
        r0[2 * (p + 1)] = d[nt][1];
        r1[2 * p]       = d[nt][2];
        r1[2 * (p + 1)] = d[nt][3];
    }
}

// ---------------- BN2 apply + ReLU ----------------
__global__ void bn_apply_kernel(float* __restrict__ out) {
    int i = blockIdx.x * 256 + threadIdx.x;
    int c = (i >> 12) & 127;
    float sc = g_bn2s[c], sh = g_bn2b[c];
    float4 v = ((float4*)out)[i];
    v.x = fmaxf(v.x * sc + sh, 0.f);
    v.y = fmaxf(v.y * sc + sh, 0.f);
    v.z = fmaxf(v.z * sc + sh, 0.f);
    v.w = fmaxf(v.w * sc + sh, 0.f);
    ((float4*)out)[i] = v;
}

// ---------------- launch ----------------
extern "C" void kernel_launch(void* const* d_in, const int* in_sizes, int n_in,
                              void* d_out, int out_size) {
    const float* x     = (const float*)d_in[0];
    const float* off_w = (const float*)d_in[1];
    const float* off_b = (const float*)d_in[2];
    const float* dcn_w = (const float*)d_in[3];
    const float* dcn_b = (const float*)d_in[4];
    const float* bn1_g = (const float*)d_in[5];
    const float* bn1_b = (const float*)d_in[6];
    const float* up_w  = (const float*)d_in[7];
    const float* bn2_g = (const float*)d_in[8];
    const float* bn2_b = (const float*)d_in[9];
    float* out = (float*)d_out;

    prep_kernel<<<288, 256>>>(dcn_w, up_w);
    nhwc_kernel<<<dim3(128, 8, 4), dim3(32, 8)>>>(x);
    offset_conv_kernel<<<256, 512>>>(x, off_w, off_b);
    deform_kernel<<<512, 256>>>(dcn_b);
    bn_partial_kernel<<<512, 128>>>(nullptr, 0);
    bn_final_kernel<<<1, 128>>>(bn1_g, bn1_b, 0);
    transp_kernel<<<1024, 256>>>(out);
    bn_partial_kernel<<<512, 128>>>(out, 1);
    bn_final_kernel<<<1, 128>>>(bn2_g, bn2_b, 1);
    bn_apply_kernel<<<8192, 256>>>(out);
}